// round 1
// baseline (speedup 1.0000x reference)
#include <cuda_runtime.h>
#include <cstdint>
#include <math.h>

#define BATCH 16
#define NN 1024
#define DD 256
#define HH 128

// Scratch (allocation-free rule: static __device__ globals)
__device__ float g_gate[BATCH * NN];
__device__ float g_axin[BATCH * NN * DD];
__device__ float g_axout[BATCH * NN * DD];
__device__ float g_xbuf[BATCH * NN * DD];

__device__ __forceinline__ float tf32f(float x) {
    uint32_t u;
    asm("cvt.rna.tf32.f32 %0, %1;" : "=r"(u) : "f"(x));
    return __uint_as_float(u);
}

__device__ __forceinline__ void mma8(float* c, const uint32_t* a, const uint32_t* b) {
    asm volatile(
        "mma.sync.aligned.m16n8k8.row.col.f32.tf32.tf32.f32 "
        "{%0,%1,%2,%3}, {%4,%5,%6,%7}, {%8,%9}, {%0,%1,%2,%3};"
        : "+f"(c[0]), "+f"(c[1]), "+f"(c[2]), "+f"(c[3])
        : "r"(a[0]), "r"(a[1]), "r"(a[2]), "r"(a[3]), "r"(b[0]), "r"(b[1]));
}

// ---------------------------------------------------------------------------
// K1: gate g = sigmoid(x @ rg)   (one warp per row)
// ---------------------------------------------------------------------------
__global__ void gate_kernel(const float* __restrict__ x, const float* __restrict__ rg) {
    int row = blockIdx.x * 8 + threadIdx.y;
    int lane = threadIdx.x;
    const float* xr = x + (size_t)row * DD;
    float s = 0.f;
#pragma unroll
    for (int i = 0; i < 8; i++) s += xr[lane + i * 32] * rg[lane + i * 32];
#pragma unroll
    for (int o = 16; o; o >>= 1) s += __shfl_xor_sync(0xffffffffu, s, o);
    if (lane == 0) g_gate[row] = 1.f / (1.f + expf(-s));
}

// ---------------------------------------------------------------------------
// K2/K3: dual GEMM (dep@x and lat@x, or transposed) blended by gate in epilogue
//   out[i,d] = g[i]*(dep(@/ᵀ)x)[i,d] + (1-g[i])*(lat(@/ᵀ)x)[i,d]
// Tile: BM=64 x BN=128, BK=32. 8 warps (2x4), warp tile 32x32. TF32 mma.
// ---------------------------------------------------------------------------
template <bool TRANS>
__global__ __launch_bounds__(256) void ax_gemm(const float* __restrict__ dep,
                                               const float* __restrict__ lat,
                                               const float* __restrict__ x) {
    constexpr int BM = 64, BN = 128, BK = 32;
    constexpr int SA = 36, SB = 136;  // padded strides (conflict-free frag reads)
    __shared__ float sD[BM * SA];
    __shared__ float sL[BM * SA];
    __shared__ float sX[BK * SB];

    const int b = blockIdx.z;
    const int m0 = blockIdx.y * BM;
    const int n0 = blockIdx.x * BN;
    const float* depb = dep + (size_t)b * NN * NN;
    const float* latb = lat + (size_t)b * NN * NN;
    const float* xb = x + (size_t)b * NN * DD;
    float* outb = (TRANS ? g_axout : g_axin) + (size_t)b * NN * DD;

    const int tid = threadIdx.x;
    const int lane = tid & 31;
    const int wid = tid >> 5;
    const int wm = wid & 1;   // 2 warps in M
    const int wn = wid >> 1;  // 4 warps in N

    float accD[2][4][4] = {};
    float accL[2][4][4] = {};

    for (int k0 = 0; k0 < NN; k0 += BK) {
        if (!TRANS) {
            // A tiles: [m][k], rows contiguous in k
#pragma unroll
            for (int it = 0; it < 2; it++) {
                int idx = tid + it * 256;          // 512 float4
                int r = idx >> 3, c4 = idx & 7;
                float4 vD = *(const float4*)(depb + (size_t)(m0 + r) * NN + k0 + c4 * 4);
                float4 vL = *(const float4*)(latb + (size_t)(m0 + r) * NN + k0 + c4 * 4);
                float4 wD = make_float4(tf32f(vD.x), tf32f(vD.y), tf32f(vD.z), tf32f(vD.w));
                float4 wL = make_float4(tf32f(vL.x), tf32f(vL.y), tf32f(vL.z), tf32f(vL.w));
                *(float4*)(sD + r * SA + c4 * 4) = wD;
                *(float4*)(sL + r * SA + c4 * 4) = wL;
            }
        } else {
            // A' = Aᵀ: sA[m][k] = A[k0+k][m0+m]; contiguous global reads, transposed store
#pragma unroll
            for (int it = 0; it < 2; it++) {
                int idx = tid + it * 256;          // 512 float4
                int kk = idx >> 4, c4 = idx & 15;  // m = c4*4..+3
                float4 vD = *(const float4*)(depb + (size_t)(k0 + kk) * NN + m0 + c4 * 4);
                float4 vL = *(const float4*)(latb + (size_t)(k0 + kk) * NN + m0 + c4 * 4);
                int m = c4 * 4;
                sD[(m + 0) * SA + kk] = tf32f(vD.x);
                sD[(m + 1) * SA + kk] = tf32f(vD.y);
                sD[(m + 2) * SA + kk] = tf32f(vD.z);
                sD[(m + 3) * SA + kk] = tf32f(vD.w);
                sL[(m + 0) * SA + kk] = tf32f(vL.x);
                sL[(m + 1) * SA + kk] = tf32f(vL.y);
                sL[(m + 2) * SA + kk] = tf32f(vL.z);
                sL[(m + 3) * SA + kk] = tf32f(vL.w);
            }
        }
        // X tile: [k][n]
#pragma unroll
        for (int it = 0; it < 4; it++) {
            int idx = tid + it * 256;           // 1024 float4
            int kk = idx >> 5, c4 = idx & 31;
            float4 v = *(const float4*)(xb + (size_t)(k0 + kk) * DD + n0 + c4 * 4);
            float4 w = make_float4(tf32f(v.x), tf32f(v.y), tf32f(v.z), tf32f(v.w));
            *(float4*)(sX + kk * SB + c4 * 4) = w;
        }
        __syncthreads();

#pragma unroll
        for (int k8 = 0; k8 < BK / 8; k8++) {
            const int kb = k8 * 8;
            uint32_t aD[2][4], aL[2][4], bx[4][2];
#pragma unroll
            for (int mt = 0; mt < 2; mt++) {
                int r = wm * 32 + mt * 16 + (lane >> 2);
                int c = kb + (lane & 3);
                aD[mt][0] = __float_as_uint(sD[r * SA + c]);
                aD[mt][1] = __float_as_uint(sD[(r + 8) * SA + c]);
                aD[mt][2] = __float_as_uint(sD[r * SA + c + 4]);
                aD[mt][3] = __float_as_uint(sD[(r + 8) * SA + c + 4]);
                aL[mt][0] = __float_as_uint(sL[r * SA + c]);
                aL[mt][1] = __float_as_uint(sL[(r + 8) * SA + c]);
                aL[mt][2] = __float_as_uint(sL[r * SA + c + 4]);
                aL[mt][3] = __float_as_uint(sL[(r + 8) * SA + c + 4]);
            }
#pragma unroll
            for (int nt = 0; nt < 4; nt++) {
                int n = wn * 32 + nt * 8 + (lane >> 2);
                int c = kb + (lane & 3);
                bx[nt][0] = __float_as_uint(sX[c * SB + n]);
                bx[nt][1] = __float_as_uint(sX[(c + 4) * SB + n]);
            }
#pragma unroll
            for (int mt = 0; mt < 2; mt++)
#pragma unroll
                for (int nt = 0; nt < 4; nt++) {
                    mma8(accD[mt][nt], aD[mt], bx[nt]);
                    mma8(accL[mt][nt], aL[mt], bx[nt]);
                }
        }
        __syncthreads();
    }

    // Epilogue: blend with per-row gate, write fp32
#pragma unroll
    for (int mt = 0; mt < 2; mt++) {
        int r0 = wm * 32 + mt * 16 + (lane >> 2);
        float g0 = g_gate[b * NN + m0 + r0];
        float g1 = g_gate[b * NN + m0 + r0 + 8];
#pragma unroll
        for (int nt = 0; nt < 4; nt++) {
            int c = n0 + wn * 32 + nt * 8 + (lane & 3) * 2;
            float2 o0, o1;
            o0.x = g0 * accD[mt][nt][0] + (1.f - g0) * accL[mt][nt][0];
            o0.y = g0 * accD[mt][nt][1] + (1.f - g0) * accL[mt][nt][1];
            o1.x = g1 * accD[mt][nt][2] + (1.f - g1) * accL[mt][nt][2];
            o1.y = g1 * accD[mt][nt][3] + (1.f - g1) * accL[mt][nt][3];
            *(float2*)(outb + (size_t)(m0 + r0) * DD + c) = o0;
            *(float2*)(outb + (size_t)(m0 + r0 + 8) * DD + c) = o1;
        }
    }
}

// ---------------------------------------------------------------------------
// K4: per-row scalar gates + residual:
//   u = Ax * sigmoid(Ax·Wg) + bg + x   (in place, both in/out streams)
// ---------------------------------------------------------------------------
__global__ void gatefc_kernel(const float* __restrict__ x,
                              const float* __restrict__ wgi, const float* __restrict__ wgo,
                              const float* __restrict__ bgi, const float* __restrict__ bgo) {
    int row = blockIdx.x * 8 + threadIdx.y;
    int lane = threadIdx.x;
    size_t base = (size_t)row * DD;
    float ai[8], ao[8], xv[8];
    float si = 0.f, so = 0.f;
#pragma unroll
    for (int i = 0; i < 8; i++) {
        int d = lane + i * 32;
        ai[i] = g_axin[base + d];
        ao[i] = g_axout[base + d];
        xv[i] = x[base + d];
        si += ai[i] * wgi[d];
        so += ao[i] * wgo[d];
    }
#pragma unroll
    for (int o = 16; o; o >>= 1) {
        si += __shfl_xor_sync(0xffffffffu, si, o);
        so += __shfl_xor_sync(0xffffffffu, so, o);
    }
    si = 1.f / (1.f + expf(-si));
    so = 1.f / (1.f + expf(-so));
    float bi = bgi[0], bo = bgo[0];
#pragma unroll
    for (int i = 0; i < 8; i++) {
        int d = lane + i * 32;
        g_axin[base + d] = ai[i] * si + bi + xv[i];
        g_axout[base + d] = ao[i] * so + bo + xv[i];
    }
}

// ---------------------------------------------------------------------------
// K5: h_in = u_in @ Wiᵀ + 2bi ; h_out = u_out @ Woᵀ + 2bo ;
//     h = concat -> LayerNorm(256) -> exact GELU -> x_next
// Block: 32 rows x full 256 h-cols. 8 warps: warps 0-3 do h_in, 4-7 do h_out.
// ---------------------------------------------------------------------------
__global__ __launch_bounds__(256) void hfuse_kernel(
    const float* __restrict__ Wi, const float* __restrict__ Wo,
    const float* __restrict__ bi, const float* __restrict__ bo,
    const float* __restrict__ lng, const float* __restrict__ lnb,
    float* __restrict__ out) {
    constexpr int BM = 32, BK = 32, SA = 36, SH = 264;
    __shared__ float sU[2 * BM * SA];
    __shared__ float sW[2 * HH * SA];  // reused as sH[BM][SH] in epilogue

    const int row0 = blockIdx.x * BM;
    const int tid = threadIdx.x;
    const int lane = tid & 31;
    const int wid = tid >> 5;
    const int side = wid >> 2;        // 0: h_in, 1: h_out
    const int nb = (wid & 3) * 32;    // 32 cols per warp within the 128 half

    float acc[2][4][4] = {};
    const float* Uglob[2] = {g_axin, g_axout};
    const float* Wglob[2] = {Wi, Wo};

    for (int k0 = 0; k0 < DD; k0 += BK) {
#pragma unroll
        for (int s = 0; s < 2; s++) {
            int r = tid >> 3, c4 = tid & 7;  // 256 float4 = 32 rows x 8
            float4 v = *(const float4*)(Uglob[s] + (size_t)(row0 + r) * DD + k0 + c4 * 4);
            float4 w = make_float4(tf32f(v.x), tf32f(v.y), tf32f(v.z), tf32f(v.w));
            *(float4*)(sU + s * BM * SA + r * SA + c4 * 4) = w;
        }
#pragma unroll
        for (int s = 0; s < 2; s++)
#pragma unroll
            for (int it = 0; it < 4; it++) {
                int idx = tid + it * 256;  // 1024 float4 = 128 rows x 8
                int h = idx >> 3, c4 = idx & 7;
                float4 v = *(const float4*)(Wglob[s] + (size_t)h * DD + k0 + c4 * 4);
                float4 w = make_float4(tf32f(v.x), tf32f(v.y), tf32f(v.z), tf32f(v.w));
                *(float4*)(sW + s * HH * SA + h * SA + c4 * 4) = w;
            }
        __syncthreads();

        const float* su = sU + side * BM * SA;
        const float* sw = sW + side * HH * SA;
#pragma unroll
        for (int k8 = 0; k8 < 4; k8++) {
            int kb = k8 * 8;
            uint32_t a[2][4], bb[4][2];
#pragma unroll
            for (int mt = 0; mt < 2; mt++) {
                int r = mt * 16 + (lane >> 2);
                int c = kb + (lane & 3);
                a[mt][0] = __float_as_uint(su[r * SA + c]);
                a[mt][1] = __float_as_uint(su[(r + 8) * SA + c]);
                a[mt][2] = __float_as_uint(su[r * SA + c + 4]);
                a[mt][3] = __float_as_uint(su[(r + 8) * SA + c + 4]);
            }
#pragma unroll
            for (int nt = 0; nt < 4; nt++) {
                int n = nb + nt * 8 + (lane >> 2);
                int c = kb + (lane & 3);
                bb[nt][0] = __float_as_uint(sw[n * SA + c]);
                bb[nt][1] = __float_as_uint(sw[n * SA + c + 4]);
            }
#pragma unroll
            for (int mt = 0; mt < 2; mt++)
#pragma unroll
                for (int nt = 0; nt < 4; nt++) mma8(acc[mt][nt], a[mt], bb[nt]);
        }
        __syncthreads();
    }

    // Epilogue: stage h (+ 2*bias) into shared, then LN + GELU
    float* sHp = sW;  // alias; all mma reads of sW are behind the last sync
    const float* bias = side ? bo : bi;
#pragma unroll
    for (int mt = 0; mt < 2; mt++) {
#pragma unroll
        for (int nt = 0; nt < 4; nt++) {
            int cl = nb + nt * 8 + (lane & 3) * 2;  // 0..127 within half
            float b0 = 2.f * bias[cl], b1 = 2.f * bias[cl + 1];
            int col = side * HH + cl;
            int r = mt * 16 + (lane >> 2);
            sHp[r * SH + col] = acc[mt][nt][0] + b0;
            sHp[r * SH + col + 1] = acc[mt][nt][1] + b1;
            sHp[(r + 8) * SH + col] = acc[mt][nt][2] + b0;
            sHp[(r + 8) * SH + col + 1] = acc[mt][nt][3] + b1;
        }
    }
    __syncthreads();

#pragma unroll
    for (int i = 0; i < 4; i++) {
        int r = wid * 4 + i;
        float v[8];
        float s = 0.f, sq = 0.f;
#pragma unroll
        for (int j = 0; j < 8; j++) {
            v[j] = sHp[r * SH + lane + j * 32];
            s += v[j];
            sq += v[j] * v[j];
        }
#pragma unroll
        for (int o = 16; o; o >>= 1) {
            s += __shfl_xor_sync(0xffffffffu, s, o);
            sq += __shfl_xor_sync(0xffffffffu, sq, o);
        }
        float mu = s * (1.f / 256.f);
        float var = sq * (1.f / 256.f) - mu * mu;
        float rs = rsqrtf(var + 1e-5f);
#pragma unroll
        for (int j = 0; j < 8; j++) {
            int col = lane + j * 32;
            float y = (v[j] - mu) * rs * lng[col] + lnb[col];
            float ge = 0.5f * y * (1.f + erff(y * 0.70710678118654752f));
            out[(size_t)(row0 + r) * DD + col] = ge;
        }
    }
}

// ---------------------------------------------------------------------------
extern "C" void kernel_launch(void* const* d_in, const int* in_sizes, int n_in,
                              void* d_out, int out_size) {
    (void)in_sizes; (void)n_in; (void)out_size;
    const float* x0  = (const float*)d_in[0];   // gcn_input
    const float* lat = (const float*)d_in[1];   // latent_adj
    const float* dep = (const float*)d_in[2];   // dep_adj
    const float* rg  = (const float*)d_in[3];   // refine_gate [L,D,1]
    const float* wgi = (const float*)d_in[4];   // gate_W_in  [L,D,1]
    const float* bgi = (const float*)d_in[5];   // gate_b_in  [L,1]
    const float* wgo = (const float*)d_in[6];   // gate_W_out [L,D,1]
    const float* bgo = (const float*)d_in[7];   // gate_b_out [L,1]
    const float* fiw = (const float*)d_in[8];   // fc_in_W  [L,H,D]
    const float* fib = (const float*)d_in[9];   // fc_in_b  [L,H]
    const float* fow = (const float*)d_in[10];  // fc_out_W [L,H,D]
    const float* fob = (const float*)d_in[11];  // fc_out_b [L,H]
    const float* lng = (const float*)d_in[12];  // ln_g [L,2H]
    const float* lnb = (const float*)d_in[13];  // ln_b [L,2H]
    float* out = (float*)d_out;

    float* xbuf_dev = nullptr;
    cudaGetSymbolAddress((void**)&xbuf_dev, g_xbuf);

    for (int l = 0; l < 2; l++) {
        const float* x = (l == 0) ? x0 : (const float*)xbuf_dev;
        float* xo = (l == 1) ? out : xbuf_dev;
        gate_kernel<<<2048, dim3(32, 8)>>>(x, rg + l * DD);
        ax_gemm<false><<<dim3(2, 16, 16), 256>>>(dep, lat, x);
        ax_gemm<true><<<dim3(2, 16, 16), 256>>>(dep, lat, x);
        gatefc_kernel<<<2048, dim3(32, 8)>>>(x, wgi + l * DD, wgo + l * DD, bgi + l, bgo + l);
        hfuse_kernel<<<512, 256>>>(fiw + (size_t)l * HH * DD, fow + (size_t)l * HH * DD,
                                   fib + l * HH, fob + l * HH,
                                   lng + l * 2 * HH, lnb + l * 2 * HH, xo);
    }
}

// round 3
// speedup vs baseline: 1.2863x; 1.2863x over previous
#include <cuda_runtime.h>
#include <cstdint>
#include <math.h>

#define BATCH 16
#define NN 1024
#define DD 256
#define HH 128

// Scratch (allocation-free rule: static __device__ globals)
__device__ float g_gate[BATCH * NN];
__device__ float g_axin[BATCH * NN * DD];
__device__ float g_axout[BATCH * NN * DD];
__device__ float g_xbuf[BATCH * NN * DD];
__device__ float g_xr[BATCH * NN * DD];   // x pre-rounded to tf32
__device__ float g_xT[BATCH * DD * NN];   // x transposed + pre-rounded

__device__ __forceinline__ float tf32f(float x) {
    uint32_t u;
    asm("cvt.rna.tf32.f32 %0, %1;" : "=r"(u) : "f"(x));
    return __uint_as_float(u);
}
__device__ __forceinline__ uint32_t smem_u32(const void* p) {
    uint32_t a;
    asm("{ .reg .u64 t; cvta.to.shared.u64 t, %1; cvt.u32.u64 %0, t; }" : "=r"(a) : "l"(p));
    return a;
}
__device__ __forceinline__ void mma8(float* c, const uint32_t* a, const uint32_t* b) {
    asm volatile(
        "mma.sync.aligned.m16n8k8.row.col.f32.tf32.tf32.f32 "
        "{%0,%1,%2,%3}, {%4,%5,%6,%7}, {%8,%9}, {%0,%1,%2,%3};"
        : "+f"(c[0]), "+f"(c[1]), "+f"(c[2]), "+f"(c[3])
        : "r"(a[0]), "r"(a[1]), "r"(a[2]), "r"(a[3]), "r"(b[0]), "r"(b[1]));
}
#define CP16(dst, src) \
    asm volatile("cp.async.cg.shared.global [%0], [%1], 16;" :: "r"(dst), "l"(src))
#define CPCOMMIT() asm volatile("cp.async.commit_group;" ::: "memory")
#define CPWAIT1() asm volatile("cp.async.wait_group 1;" ::: "memory")

// ---------------------------------------------------------------------------
// xprep: g_xr = tf32-rounded x ; g_xT = tf32-rounded transpose of x
// ---------------------------------------------------------------------------
__global__ void xprep_k(const float* __restrict__ x) {
    __shared__ float t[32][33];
    int b = blockIdx.z;
    int c0 = blockIdx.x * 32, r0 = blockIdx.y * 32;
    const float* xb = x + (size_t)b * NN * DD;
    float* xrb = g_xr + (size_t)b * NN * DD;
    float* xtb = g_xT + (size_t)b * DD * NN;
    int tx = threadIdx.x, ty = threadIdx.y;
#pragma unroll
    for (int i = 0; i < 4; i++) {
        float v = tf32f(xb[(size_t)(r0 + ty + 8 * i) * DD + c0 + tx]);
        t[ty + 8 * i][tx] = v;
        xrb[(size_t)(r0 + ty + 8 * i) * DD + c0 + tx] = v;
    }
    __syncthreads();
#pragma unroll
    for (int i = 0; i < 4; i++)
        xtb[(size_t)(c0 + ty + 8 * i) * NN + r0 + tx] = t[tx][ty + 8 * i];
}

// ---------------------------------------------------------------------------
// K1: gate g = sigmoid(x @ rg)   (one warp per row)
// ---------------------------------------------------------------------------
__global__ void gate_kernel(const float* __restrict__ x, const float* __restrict__ rg) {
    int row = blockIdx.x * 8 + threadIdx.y;
    int lane = threadIdx.x;
    const float* xr = x + (size_t)row * DD;
    float s = 0.f;
#pragma unroll
    for (int i = 0; i < 8; i++) s += xr[lane + i * 32] * rg[lane + i * 32];
#pragma unroll
    for (int o = 16; o; o >>= 1) s += __shfl_xor_sync(0xffffffffu, s, o);
    if (lane == 0) g_gate[row] = 1.f / (1.f + expf(-s));
}

// ---------------------------------------------------------------------------
// N-GEMM: axin[i,:] = g[i]*(dep@xr)[i,:] + (1-g[i])*(lat@xr)[i,:]
// BM=64, BN=256(full D), BK=32. 256 thr, 8 warps (2m x 4n), warp m32 x n64.
// 3-stage cp.async pipeline. Adjacency frags cvt'd to tf32; x pre-rounded.
// ---------------------------------------------------------------------------
#define N_STAGE 52224   // sD 9216 + sL 9216 + sX 33792
#define N_SMEM (3 * N_STAGE)

__global__ __launch_bounds__(256, 1) void axn_tc(const float* __restrict__ dep,
                                                 const float* __restrict__ lat) {
    extern __shared__ char smem[];
    const uint32_t sb = smem_u32(smem);
    const int tid = threadIdx.x, lane = tid & 31, wid = tid >> 5;
    const int b = blockIdx.y, m0 = blockIdx.x * 64;
    const float* A1 = dep + (size_t)b * NN * NN + (size_t)m0 * NN;
    const float* A2 = lat + (size_t)b * NN * NN + (size_t)m0 * NN;
    const float* xb = g_xr + (size_t)b * NN * DD;

    auto issue = [&](int it) {
        const uint32_t so = sb + (it % 3) * N_STAGE;
        const int k0 = it * 32;
#pragma unroll
        for (int i = 0; i < 2; i++) {
            int idx = tid + i * 256;
            int r = idx >> 3, c = idx & 7;
            CP16(so + r * 144 + c * 16, A1 + (size_t)r * NN + k0 + c * 4);
            CP16(so + 9216 + r * 144 + c * 16, A2 + (size_t)r * NN + k0 + c * 4);
        }
#pragma unroll
        for (int i = 0; i < 8; i++) {
            int idx = tid + i * 256;
            int r = idx >> 6, c = idx & 63;
            CP16(so + 18432 + r * 1056 + c * 16, xb + (size_t)(k0 + r) * DD + c * 4);
        }
        CPCOMMIT();
    };

    issue(0);
    issue(1);

    float accD[2][8][4] = {};
    float accL[2][8][4] = {};
    const int wm = wid & 1, wn = wid >> 1;

    for (int it = 0; it < 32; it++) {
        CPWAIT1();
        __syncthreads();
        if (it + 2 < 32) issue(it + 2); else CPCOMMIT();
        const char* st = smem + (it % 3) * N_STAGE;
        const float* sD = (const float*)st;
        const float* sL = (const float*)(st + 9216);
        const float* sX = (const float*)(st + 18432);
#pragma unroll
        for (int k8 = 0; k8 < 4; k8++) {
            const int c = k8 * 8 + (lane & 3);
            uint32_t aD[2][4], aL[2][4], bx[8][2];
#pragma unroll
            for (int mt = 0; mt < 2; mt++) {
                int r = wm * 32 + mt * 16 + (lane >> 2);
                aD[mt][0] = __float_as_uint(tf32f(sD[r * 36 + c]));
                aD[mt][1] = __float_as_uint(tf32f(sD[(r + 8) * 36 + c]));
                aD[mt][2] = __float_as_uint(tf32f(sD[r * 36 + c + 4]));
                aD[mt][3] = __float_as_uint(tf32f(sD[(r + 8) * 36 + c + 4]));
                aL[mt][0] = __float_as_uint(tf32f(sL[r * 36 + c]));
                aL[mt][1] = __float_as_uint(tf32f(sL[(r + 8) * 36 + c]));
                aL[mt][2] = __float_as_uint(tf32f(sL[r * 36 + c + 4]));
                aL[mt][3] = __float_as_uint(tf32f(sL[(r + 8) * 36 + c + 4]));
            }
#pragma unroll
            for (int nt = 0; nt < 8; nt++) {
                int n = wn * 64 + nt * 8 + (lane >> 2);
                bx[nt][0] = __float_as_uint(sX[c * 264 + n]);
                bx[nt][1] = __float_as_uint(sX[(c + 4) * 264 + n]);
            }
#pragma unroll
            for (int mt = 0; mt < 2; mt++)
#pragma unroll
                for (int nt = 0; nt < 8; nt++) {
                    mma8(accD[mt][nt], aD[mt], bx[nt]);
                    mma8(accL[mt][nt], aL[mt], bx[nt]);
                }
        }
    }

    // epilogue: blend with per-row gate
#pragma unroll
    for (int mt = 0; mt < 2; mt++) {
        int r0 = wm * 32 + mt * 16 + (lane >> 2);
        float g0 = g_gate[b * NN + m0 + r0];
        float g1 = g_gate[b * NN + m0 + r0 + 8];
        float* o0 = g_axin + (size_t)b * NN * DD + (size_t)(m0 + r0) * DD;
        float* o1 = o0 + 8 * DD;
#pragma unroll
        for (int nt = 0; nt < 8; nt++) {
            int c = wn * 64 + nt * 8 + (lane & 3) * 2;
            float2 v0, v1;
            v0.x = g0 * accD[mt][nt][0] + (1.f - g0) * accL[mt][nt][0];
            v0.y = g0 * accD[mt][nt][1] + (1.f - g0) * accL[mt][nt][1];
            v1.x = g1 * accD[mt][nt][2] + (1.f - g1) * accL[mt][nt][2];
            v1.y = g1 * accD[mt][nt][3] + (1.f - g1) * accL[mt][nt][3];
            *(float2*)(o0 + c) = v0;
            *(float2*)(o1 + c) = v1;
        }
    }
}

// ---------------------------------------------------------------------------
// T-GEMM: computes (xT @ dep) and (xT @ lat), blends with g per column (node),
// writes transposed: axout[i][d] = g[i]*(depT@x)[i][d] + (1-g[i])*(latT@x)[i][d]
// BM=128 (features), BN=128 (nodes), BK=32. 256 thr, warps 2m x 4n (m64 x n32).
// ---------------------------------------------------------------------------
#define T_STAGE 53248   // sA 18432 + sBD 17408 + sBL 17408
#define T_SMEM (3 * T_STAGE)

__global__ __launch_bounds__(256, 1) void axt_tc(const float* __restrict__ dep,
                                                 const float* __restrict__ lat) {
    extern __shared__ char smem[];
    const uint32_t sb = smem_u32(smem);
    const int tid = threadIdx.x, lane = tid & 31, wid = tid >> 5;
    const int b = blockIdx.z, n0 = blockIdx.x * 128, m0 = blockIdx.y * 128;
    const float* Ab = g_xT + (size_t)b * DD * NN + (size_t)m0 * NN;
    const float* B1 = dep + (size_t)b * NN * NN;
    const float* B2 = lat + (size_t)b * NN * NN;

    auto issue = [&](int it) {
        const uint32_t so = sb + (it % 3) * T_STAGE;
        const int k0 = it * 32;
#pragma unroll
        for (int i = 0; i < 4; i++) {
            int idx = tid + i * 256;
            int r = idx >> 3, c = idx & 7;
            CP16(so + r * 144 + c * 16, Ab + (size_t)r * NN + k0 + c * 4);
        }
#pragma unroll
        for (int i = 0; i < 4; i++) {
            int idx = tid + i * 256;
            int r = idx >> 5, c = idx & 31;
            CP16(so + 18432 + r * 544 + c * 16, B1 + (size_t)(k0 + r) * NN + n0 + c * 4);
            CP16(so + 35840 + r * 544 + c * 16, B2 + (size_t)(k0 + r) * NN + n0 + c * 4);
        }
        CPCOMMIT();
    };

    issue(0);
    issue(1);

    float accD[4][4][4] = {};
    float accL[4][4][4] = {};
    const int wm = wid & 1, wn = wid >> 1;

    for (int it = 0; it < 32; it++) {
        CPWAIT1();
        __syncthreads();
        if (it + 2 < 32) issue(it + 2); else CPCOMMIT();
        const char* st = smem + (it % 3) * T_STAGE;
        const float* sA = (const float*)st;
        const float* sBD = (const float*)(st + 18432);
        const float* sBL = (const float*)(st + 35840);
#pragma unroll
        for (int k8 = 0; k8 < 4; k8++) {
            const int c = k8 * 8 + (lane & 3);
            uint32_t a[4][4], bD[4][2], bL[4][2];
#pragma unroll
            for (int mt = 0; mt < 4; mt++) {
                int r = wm * 64 + mt * 16 + (lane >> 2);
                a[mt][0] = __float_as_uint(sA[r * 36 + c]);
                a[mt][1] = __float_as_uint(sA[(r + 8) * 36 + c]);
                a[mt][2] = __float_as_uint(sA[r * 36 + c + 4]);
                a[mt][3] = __float_as_uint(sA[(r + 8) * 36 + c + 4]);
            }
#pragma unroll
            for (int nt = 0; nt < 4; nt++) {
                int n = wn * 32 + nt * 8 + (lane >> 2);
                bD[nt][0] = __float_as_uint(tf32f(sBD[c * 136 + n]));
                bD[nt][1] = __float_as_uint(tf32f(sBD[(c + 4) * 136 + n]));
                bL[nt][0] = __float_as_uint(tf32f(sBL[c * 136 + n]));
                bL[nt][1] = __float_as_uint(tf32f(sBL[(c + 4) * 136 + n]));
            }
#pragma unroll
            for (int mt = 0; mt < 4; mt++)
#pragma unroll
                for (int nt = 0; nt < 4; nt++) {
                    mma8(accD[mt][nt], a[mt], bD[nt]);
                    mma8(accL[mt][nt], a[mt], bL[nt]);
                }
        }
    }

    // epilogue: blend by column (node) gate, transpose via smem, coalesced write
    __syncthreads();
    float* sbuf = (float*)smem;   // [node 128][feat 132]
#pragma unroll
    for (int mt = 0; mt < 4; mt++) {
        int r = wm * 64 + mt * 16 + (lane >> 2);
#pragma unroll
        for (int nt = 0; nt < 4; nt++) {
            int c = wn * 32 + nt * 8 + (lane & 3) * 2;
            float g0 = g_gate[b * NN + n0 + c];
            float g1 = g_gate[b * NN + n0 + c + 1];
            sbuf[c * 132 + r] = g0 * accD[mt][nt][0] + (1.f - g0) * accL[mt][nt][0];
            sbuf[(c + 1) * 132 + r] = g1 * accD[mt][nt][1] + (1.f - g1) * accL[mt][nt][1];
            sbuf[c * 132 + r + 8] = g0 * accD[mt][nt][2] + (1.f - g0) * accL[mt][nt][2];
            sbuf[(c + 1) * 132 + r + 8] = g1 * accD[mt][nt][3] + (1.f - g1) * accL[mt][nt][3];
        }
    }
    __syncthreads();
    float* ob = g_axout + (size_t)b * NN * DD;
#pragma unroll
    for (int i = 0; i < 16; i++) {
        int idx = tid + i * 256;
        int row = idx >> 5, c4 = idx & 31;
        float4 v = *(const float4*)(sbuf + row * 132 + c4 * 4);
        *(float4*)(ob + (size_t)(n0 + row) * DD + m0 + c4 * 4) = v;
    }
}

// ---------------------------------------------------------------------------
// K4: per-row scalar gates + residual (in place on g_axin/g_axout)
// ---------------------------------------------------------------------------
__global__ void gatefc_kernel(const float* __restrict__ x,
                              const float* __restrict__ wgi, const float* __restrict__ wgo,
                              const float* __restrict__ bgi, const float* __restrict__ bgo) {
    int row = blockIdx.x * 8 + threadIdx.y;
    int lane = threadIdx.x;
    size_t base = (size_t)row * DD;
    float ai[8], ao[8], xv[8];
    float si = 0.f, so = 0.f;
#pragma unroll
    for (int i = 0; i < 8; i++) {
        int d = lane + i * 32;
        ai[i] = g_axin[base + d];
        ao[i] = g_axout[base + d];
        xv[i] = x[base + d];
        si += ai[i] * wgi[d];
        so += ao[i] * wgo[d];
    }
#pragma unroll
    for (int o = 16; o; o >>= 1) {
        si += __shfl_xor_sync(0xffffffffu, si, o);
        so += __shfl_xor_sync(0xffffffffu, so, o);
    }
    si = 1.f / (1.f + expf(-si));
    so = 1.f / (1.f + expf(-so));
    float bi = bgi[0], bo = bgo[0];
#pragma unroll
    for (int i = 0; i < 8; i++) {
        int d = lane + i * 32;
        g_axin[base + d] = ai[i] * si + bi + xv[i];
        g_axout[base + d] = ao[i] * so + bo + xv[i];
    }
}

// ---------------------------------------------------------------------------
// K5: h = concat(u_in@WiT + 2bi, u_out@WoT + 2bo) -> LN(256) -> exact GELU
// ---------------------------------------------------------------------------
__global__ __launch_bounds__(256) void hfuse_kernel(
    const float* __restrict__ Wi, const float* __restrict__ Wo,
    const float* __restrict__ bi, const float* __restrict__ bo,
    const float* __restrict__ lng, const float* __restrict__ lnb,
    float* __restrict__ out) {
    constexpr int BM = 32, BK = 32, SA = 36, SH = 264;
    __shared__ float sU[2 * BM * SA];
    __shared__ float sW[2 * HH * SA];  // reused as sH[BM][SH] in epilogue

    const int row0 = blockIdx.x * BM;
    const int tid = threadIdx.x;
    const int lane = tid & 31;
    const int wid = tid >> 5;
    const int side = wid >> 2;
    const int nb = (wid & 3) * 32;

    float acc[2][4][4] = {};
    const float* Uglob[2] = {g_axin, g_axout};
    const float* Wglob[2] = {Wi, Wo};

    for (int k0 = 0; k0 < DD; k0 += BK) {
#pragma unroll
        for (int s = 0; s < 2; s++) {
            int r = tid >> 3, c4 = tid & 7;
            float4 v = *(const float4*)(Uglob[s] + (size_t)(row0 + r) * DD + k0 + c4 * 4);
            float4 w = make_float4(tf32f(v.x), tf32f(v.y), tf32f(v.z), tf32f(v.w));
            *(float4*)(sU + s * BM * SA + r * SA + c4 * 4) = w;
        }
#pragma unroll
        for (int s = 0; s < 2; s++)
#pragma unroll
            for (int it = 0; it < 4; it++) {
                int idx = tid + it * 256;
                int h = idx >> 3, c4 = idx & 7;
                float4 v = *(const float4*)(Wglob[s] + (size_t)h * DD + k0 + c4 * 4);
                float4 w = make_float4(tf32f(v.x), tf32f(v.y), tf32f(v.z), tf32f(v.w));
                *(float4*)(sW + s * HH * SA + h * SA + c4 * 4) = w;
            }
        __syncthreads();

        const float* su = sU + side * BM * SA;
        const float* sw = sW + side * HH * SA;
#pragma unroll
        for (int k8 = 0; k8 < 4; k8++) {
            int kb = k8 * 8;
            uint32_t a[2][4], bb[4][2];
#pragma unroll
            for (int mt = 0; mt < 2; mt++) {
                int r = mt * 16 + (lane >> 2);
                int c = kb + (lane & 3);
                a[mt][0] = __float_as_uint(su[r * SA + c]);
                a[mt][1] = __float_as_uint(su[(r + 8) * SA + c]);
                a[mt][2] = __float_as_uint(su[r * SA + c + 4]);
                a[mt][3] = __float_as_uint(su[(r + 8) * SA + c + 4]);
            }
#pragma unroll
            for (int nt = 0; nt < 4; nt++) {
                int n = nb + nt * 8 + (lane >> 2);
                int c = kb + (lane & 3);
                bb[nt][0] = __float_as_uint(sw[n * SA + c]);
                bb[nt][1] = __float_as_uint(sw[n * SA + c + 4]);
            }
#pragma unroll
            for (int mt = 0; mt < 2; mt++)
#pragma unroll
                for (int nt = 0; nt < 4; nt++) mma8(acc[mt][nt], a[mt], bb[nt]);
        }
        __syncthreads();
    }

    float* sHp = sW;
    const float* bias = side ? bo : bi;
#pragma unroll
    for (int mt = 0; mt < 2; mt++) {
#pragma unroll
        for (int nt = 0; nt < 4; nt++) {
            int cl = nb + nt * 8 + (lane & 3) * 2;
            float b0 = 2.f * bias[cl], b1 = 2.f * bias[cl + 1];
            int col = side * HH + cl;
            int r = mt * 16 + (lane >> 2);
            sHp[r * SH + col] = acc[mt][nt][0] + b0;
            sHp[r * SH + col + 1] = acc[mt][nt][1] + b1;
            sHp[(r + 8) * SH + col] = acc[mt][nt][2] + b0;
            sHp[(r + 8) * SH + col + 1] = acc[mt][nt][3] + b1;
        }
    }
    __syncthreads();

#pragma unroll
    for (int i = 0; i < 4; i++) {
        int r = wid * 4 + i;
        float v[8];
        float s = 0.f, sq = 0.f;
#pragma unroll
        for (int j = 0; j < 8; j++) {
            v[j] = sHp[r * SH + lane + j * 32];
            s += v[j];
            sq += v[j] * v[j];
        }
#pragma unroll
        for (int o = 16; o; o >>= 1) {
            s += __shfl_xor_sync(0xffffffffu, s, o);
            sq += __shfl_xor_sync(0xffffffffu, sq, o);
        }
        float mu = s * (1.f / 256.f);
        float var = sq * (1.f / 256.f) - mu * mu;
        float rs = rsqrtf(var + 1e-5f);
#pragma unroll
        for (int j = 0; j < 8; j++) {
            int col = lane + j * 32;
            float y = (v[j] - mu) * rs * lng[col] + lnb[col];
            float ge = 0.5f * y * (1.f + erff(y * 0.70710678118654752f));
            out[(size_t)(row0 + r) * DD + col] = ge;
        }
    }
}

// ---------------------------------------------------------------------------
extern "C" void kernel_launch(void* const* d_in, const int* in_sizes, int n_in,
                              void* d_out, int out_size) {
    (void)in_sizes; (void)n_in; (void)out_size;
    const float* x0  = (const float*)d_in[0];
    const float* lat = (const float*)d_in[1];
    const float* dep = (const float*)d_in[2];
    const float* rg  = (const float*)d_in[3];
    const float* wgi = (const float*)d_in[4];
    const float* bgi = (const float*)d_in[5];
    const float* wgo = (const float*)d_in[6];
    const float* bgo = (const float*)d_in[7];
    const float* fiw = (const float*)d_in[8];
    const float* fib = (const float*)d_in[9];
    const float* fow = (const float*)d_in[10];
    const float* fob = (const float*)d_in[11];
    const float* lng = (const float*)d_in[12];
    const float* lnb = (const float*)d_in[13];
    float* out = (float*)d_out;

    float* xbuf_p = nullptr;
    cudaGetSymbolAddress((void**)&xbuf_p, g_xbuf);

    cudaFuncSetAttribute(axn_tc, cudaFuncAttributeMaxDynamicSharedMemorySize, N_SMEM);
    cudaFuncSetAttribute(axt_tc, cudaFuncAttributeMaxDynamicSharedMemorySize, T_SMEM);

    for (int l = 0; l < 2; l++) {
        const float* x = (l == 0) ? x0 : (const float*)xbuf_p;
        float* xo = (l == 1) ? out : xbuf_p;
        gate_kernel<<<2048, dim3(32, 8)>>>(x, rg + l * DD);
        xprep_k<<<dim3(8, 32, 16), dim3(32, 8)>>>(x);
        axn_tc<<<dim3(16, 16), 256, N_SMEM>>>(dep, lat);
        axt_tc<<<dim3(8, 2, 16), 256, T_SMEM>>>(dep, lat);
        gatefc_kernel<<<2048, dim3(32, 8)>>>(x, wgi + l * DD, wgo + l * DD, bgi + l, bgo + l);
        hfuse_kernel<<<512, 256>>>(fiw + (size_t)l * HH * DD, fow + (size_t)l * HH * DD,
                                   fib + l * HH, fob + l * HH,
                                   lng + l * 2 * HH, lnb + l * 2 * HH, xo);
    }
}